// round 9
// baseline (speedup 1.0000x reference)
#include <cuda_runtime.h>

// Problem constants
#define B_  4
#define P_  64
#define S_  8
#define YD  16
#define GD  48
#define N_OUT  (B_ * P_ * P_ * S_ * S_)   // 1048576

// Wg lives in constant memory: FFMA operands come through the const port
// (LDC/LDCU), completely off the l1tex pipe that the pg stream saturates.
__constant__ float c_wg[GD];

// Fused kernel: per-block ky prologue (threads 0..39) + pg stream.
// Block = 256 threads = 4 q-values (q = (b*64+p1)*64+p2), so b and p1 are
// constant per block and p2 spans 4 consecutive values (never crosses p1).
__global__ void __launch_bounds__(256) fused_kernel(
    const float* __restrict__ pg,
    const float* __restrict__ y,
    const float* __restrict__ Wy,
    const float* __restrict__ by,
    const float* __restrict__ bg,
    float* __restrict__ out)
{
    __shared__ float ky1_sh[32];  // [p2_local*8 + s2]   (y @ Wy[:16])
    __shared__ float ky2_sh[8];   // [s1]                (y @ Wy[16:] + by + bg)

    const int tid    = threadIdx.x;
    const int o_base = blockIdx.x << 8;          // 256 outputs per block
    const int q_base = o_base >> 6;              // o = q*64 + (s1*8+s2)
    const int p2_base = q_base & (P_ - 1);
    const int p1      = (q_base >> 6) & (P_ - 1);
    const int b       = q_base >> 12;

    // ---- ky prologue: 40 dot products of length 16 ----
    if (tid < 40) {
        int row, woff;
        float a = 0.f;
        if (tid < 32) {                          // ky1 for (b, p2_base+p2l, s2)
            int p2l = tid >> 3, s2 = tid & 7;
            row  = (b * P_ + p2_base + p2l) * S_ + s2;
            woff = 0;
        } else {                                 // ky2 for (b, p1, s1), biases folded
            int s1 = tid - 32;
            row  = (b * P_ + p1) * S_ + s1;
            woff = YD;
            a    = by[0] + bg[0];
        }
        const float4* y4 = reinterpret_cast<const float4*>(y + (size_t)row * YD);
        const float4* w4 = reinterpret_cast<const float4*>(Wy + woff);
#pragma unroll
        for (int j = 0; j < YD / 4; j++) {
            float4 yv = __ldg(y4 + j);
            float4 wv = __ldg(w4 + j);
            a += yv.x * wv.x + yv.y * wv.y + yv.z * wv.z + yv.w * wv.w;
        }
        if (tid < 32) ky1_sh[tid] = a;
        else          ky2_sh[tid - 32] = a;
    }
    __syncthreads();

    // ---- main stream: 12 dense float4 LDGs, dot with constant-memory Wg ----
    const int o = o_base + tid;
    const float4* g4 = reinterpret_cast<const float4*>(pg + (size_t)o * GD);
    float acc = 0.f;
#pragma unroll
    for (int j = 0; j < GD / 4; j++) {
        float4 gv = __ldg(g4 + j);
        acc += gv.x * c_wg[4 * j + 0] + gv.y * c_wg[4 * j + 1]
             + gv.z * c_wg[4 * j + 2] + gv.w * c_wg[4 * j + 3];
    }

    const int r = tid & 63;                      // r = s1*8 + s2
    out[o] = acc + ky1_sh[(tid >> 6) * 8 + (r & 7)] + ky2_sh[r >> 3];
}

extern "C" void kernel_launch(void* const* d_in, const int* in_sizes, int n_in,
                              void* d_out, int out_size) {
    // metadata order: y, pairwise_g, Wy, by, Wg, bg
    const float* y  = (const float*)d_in[0];
    const float* pg = (const float*)d_in[1];
    const float* Wy = (const float*)d_in[2];
    const float* by = (const float*)d_in[3];
    const float* Wg = (const float*)d_in[4];
    const float* bg = (const float*)d_in[5];
    float* out = (float*)d_out;

    // Graph-legal D2D copy into constant memory (memcpy node).
    cudaMemcpyToSymbolAsync(c_wg, Wg, GD * sizeof(float), 0,
                            cudaMemcpyDeviceToDevice, 0);

    fused_kernel<<<N_OUT / 256, 256>>>(pg, y, Wy, by, bg, out);
}